// round 16
// baseline (speedup 1.0000x reference)
#include <cuda_runtime.h>

// TFLoudnessLoss: multi-band (8) loudness difference with softmax weighting.
// Four-step FFT:  n = n1 + 256*n2,  k = k2 + 625*k1   (L = 160000 = 256*625)
// Packing: z_s = xw[s] + i*xo[s] (8 packed signals). Band mask is conjugate-
// symmetric, so IFFT(mask_b * Z) = r_w + i*r_o directly (both real).
// Band structure: with k1 = j + 16 r, for k2>=1 band(k2+625*k1) = r<8 ? r : 15-r.
// fwd2+inv1 fused (spectrum never leaves shared). inv2: immediate W25 twiddles
// + 4 pipes batched per block (shWL table amortized, ~1 wave).

#define LTOT 160000
#define NBLK 156
#define NCH  155
#define NDIFF (8*8*155)
#define NBS 128            /* 8 bands x 16 signals (w:0-7, o:8-15) */
#define NPIPE 64           /* 8 bands x 8 packed signals */
#define NG2  52            /* inv2 n1-groups: 52*5 >= 260 >= 256 */

__device__ float2 d_W[LTOT];              // e^{-2*pi*i*m/L}
__device__ float2 d_W16[16];
__device__ float2 d_work[8*LTOT];         // fwd intermediate [s][k2*256+n1]
__device__ float2 d_work8[(size_t)NPIPE*LTOT];  // inv intermediate [b*8+s][n1*625+k2]
__device__ float  d_P[NBS*NBLK*NG2];      // partial block energies [bs][jb][g]
__device__ float  d_blk[NBS*NBLK];

__device__ __forceinline__ float2 cmulf(float2 a, float2 b){
  return make_float2(fmaf(a.x,b.x,-a.y*b.y), fmaf(a.x,b.y,a.y*b.x));
}
__device__ __forceinline__ float2 cadd(float2 a,float2 b){return make_float2(a.x+b.x,a.y+b.y);}
__device__ __forceinline__ float2 csub(float2 a,float2 b){return make_float2(a.x-b.x,a.y-b.y);}

__global__ void k_genW(){
  int m = blockIdx.x*blockDim.x + threadIdx.x;
  if (m < LTOT){
    float t = (float)((double)m / 80000.0);   // 2m/L
    float s, c;
    sincospif(t, &s, &c);
    d_W[m] = make_float2(c, -s);
  }
  if (blockIdx.x == 0 && threadIdx.x < 16){
    int q = threadIdx.x;
    float s, c; sincospif(2.f*q/16.f, &s, &c);
    d_W16[q] = make_float2(c, -s);
  }
}

template<int SIGN>
__device__ __forceinline__ void dft5(float2 v[5]){
  const float C1 = 0.30901699437494745f;
  const float S1 = 0.95105651629515353f;
  const float C2 = -0.80901699437494745f;
  const float S2 = 0.58778525229247314f;
  float2 w1 = make_float2(C1,  SIGN*S1);
  float2 w2 = make_float2(C2,  SIGN*S2);
  float2 w3 = make_float2(C2, -SIGN*S2);
  float2 w4 = make_float2(C1, -SIGN*S1);
  float2 o0 = cadd(cadd(v[0],v[1]), cadd(cadd(v[2],v[3]),v[4]));
  float2 o1 = cadd(v[0], cadd(cadd(cmulf(v[1],w1),cmulf(v[2],w2)), cadd(cmulf(v[3],w3),cmulf(v[4],w4))));
  float2 o2 = cadd(v[0], cadd(cadd(cmulf(v[1],w2),cmulf(v[2],w4)), cadd(cmulf(v[3],w1),cmulf(v[4],w3))));
  float2 o3 = cadd(v[0], cadd(cadd(cmulf(v[1],w3),cmulf(v[2],w1)), cadd(cmulf(v[3],w4),cmulf(v[4],w2))));
  float2 o4 = cadd(v[0], cadd(cadd(cmulf(v[1],w4),cmulf(v[2],w3)), cadd(cmulf(v[3],w2),cmulf(v[4],w1))));
  v[0]=o0; v[1]=o1; v[2]=o2; v[3]=o3; v[4]=o4;
}

template<int SIGN>
__device__ __forceinline__ void dft4(float2 v[4]){
  float2 s02 = cadd(v[0],v[2]), d02 = csub(v[0],v[2]);
  float2 s13 = cadd(v[1],v[3]), d13 = csub(v[1],v[3]);
  float2 id13 = make_float2(-d13.y, d13.x);
  float2 o0 = cadd(s02, s13);
  float2 o2 = csub(s02, s13);
  float2 o1, o3;
  if (SIGN < 0){ o1 = csub(d02, id13); o3 = cadd(d02, id13); }
  else         { o1 = cadd(d02, id13); o3 = csub(d02, id13); }
  v[0]=o0; v[1]=o1; v[2]=o2; v[3]=o3;
}

// conj(W25^m) = cos(2pi m/25) + i sin(2pi m/25), m compile-time (folds to imm)
__device__ __forceinline__ float2 w25im(int m){
  switch(m){
    case 1:  return make_float2( 0.96858316112863f,  0.24868988716485f);
    case 2:  return make_float2( 0.87630668004386f,  0.48175367410172f);
    case 3:  return make_float2( 0.72896862742141f,  0.68454710592869f);
    case 4:  return make_float2( 0.53582679497900f,  0.84432792550202f);
    case 6:  return make_float2( 0.06279051952931f,  0.99802672842827f);
    case 8:  return make_float2(-0.42577929156507f,  0.90482705246602f);
    case 9:  return make_float2(-0.63742398974869f,  0.77051324277579f);
    case 12: return make_float2(-0.99211470131448f,  0.12533323356430f);
    case 16: return make_float2(-0.63742398974869f, -0.77051324277579f);
    default: return make_float2(1.f, 0.f);
  }
}

// inverse DFT25 with immediate-constant twiddles
__device__ __forceinline__ void dft25i(float2 v[25]){
  float2 t[25];
  #pragma unroll
  for (int r0=0;r0<5;r0++){
    float2 a[5] = {v[r0], v[r0+5], v[r0+10], v[r0+15], v[r0+20]};
    dft5<1>(a);
    #pragma unroll
    for (int k0=0;k0<5;k0++)
      t[r0*5+k0] = (r0*k0) ? cmulf(a[k0], w25im(r0*k0)) : a[k0];
  }
  #pragma unroll
  for (int k0=0;k0<5;k0++){
    float2 b[5] = {t[k0], t[5+k0], t[10+k0], t[15+k0], t[20+k0]};
    dft5<1>(b);
    #pragma unroll
    for (int k1=0;k1<5;k1++) v[k0+5*k1] = b[k1];
  }
}

// ---------------- shared-memory Stockham FFTs ----------------

template<int SIGN>
__device__ void fft625(float2* __restrict__ A, float2* __restrict__ B, int lane){
  float2* src = A; float2* dst = B;
  int Ns = 1;
  #pragma unroll
  for (int t=0;t<4;t++){
    if (lane < 125){
      int j = lane;
      int jNs = j % Ns;
      int f = LTOT/(Ns*5);
      float2 v[5];
      #pragma unroll
      for (int r=0;r<5;r++){
        float2 x = src[j + r*125];
        int m = r*jNs*f;
        if (m){
          float2 w = d_W[m];
          if (SIGN>0) w.y = -w.y;
          x = cmulf(x,w);
        }
        v[r]=x;
      }
      dft5<SIGN>(v);
      int idxD = (j/Ns)*(Ns*5) + jNs;
      #pragma unroll
      for (int r=0;r<5;r++) dst[idxD + r*Ns] = v[r];
    }
    __syncthreads();
    float2* tmp = src; src = dst; dst = tmp;
    Ns *= 5;
  }
}

template<int SIGN>
__device__ void fft256s(float2* __restrict__ A, float2* __restrict__ B, int lane){
  float2* src = A; float2* dst = B;
  int Ns = 1;
  #pragma unroll
  for (int t=0;t<4;t++){
    {
      int j = lane;
      int jNs = j % Ns;
      int f = LTOT/(Ns*4);
      float2 v[4];
      #pragma unroll
      for (int r=0;r<4;r++){
        float2 x = src[j + r*64];
        int m = r*jNs*f;
        if (m){
          float2 w = d_W[m];
          if (SIGN>0) w.y = -w.y;
          x = cmulf(x,w);
        }
        v[r]=x;
      }
      dft4<SIGN>(v);
      int idxD = (j/Ns)*(Ns*4) + jNs;
      #pragma unroll
      for (int r=0;r<4;r++) dst[idxD + r*Ns] = v[r];
    }
    __syncthreads();
    float2* tmp = src; src = dst; dst = tmp;
    Ns *= 4;
  }
}

// ---------------- forward stage 1 ----------------

// z = xw + i*xo : 8 packed signals
__global__ void __launch_bounds__(512) k_fwd1(const float* __restrict__ xw, const float* __restrict__ xo){
  __shared__ float2 sh[4][2][625];
  int tid = threadIdx.x;
  int sub = tid >> 7, lane = tid & 127;
  int n1b = blockIdx.x*4;
  int s   = blockIdx.y;             // 0..7
  const float* xa = xw + s*LTOT;
  const float* xb = xo + s*LTOT;
  for (int w = tid; w < 2500; w += 512){
    int n2 = w >> 2, sb = w & 3;
    int n = n1b + sb + 256*n2;
    sh[sb][0][n2] = make_float2(xa[n], xb[n]);
  }
  __syncthreads();
  fft625<-1>(sh[sub][0], sh[sub][1], lane);
  float2* out = d_work + s*LTOT;
  for (int w = tid; w < 2500; w += 512){
    int k2 = w >> 2, sb = w & 3;
    int n1 = n1b + sb;
    float2 v = cmulf(sh[sb][0][k2], d_W[n1*k2]);
    out[k2*256 + n1] = v;
  }
}

// ---------------- fused forward stage 2 + inverse stage 1 ----------------
// Block: 256 threads. FFT phase: 4 k2-rows x 64 lanes (forward FFT256 over n1).
// Inverse phase: 4 rows x 4 band-groups x 16 lanes; group bg handles bands
// 2bg and 2bg+1 sequentially with the in-place IFFT16 slot scheme.
// Grid: (157 k2-groups, 8 signals).
__global__ void __launch_bounds__(256) k_f2i1(){
  __shared__ float2 sh[4][2][256];   // 16KB fft buffers; X stays in sh[row][0]
  __shared__ float2 T[16][257];      // 32.9KB: [row*4 + grp]
  __shared__ float2 shW6[256];       // conj W_L^{625*r*j}  [r*16+j]
  __shared__ float2 shAc[4][16];     // conj W_L^{k2*l},    l<16
  __shared__ float2 shBc[4][16];     // conj W_L^{k2*16*h}, h<16
  __shared__ float2 shW16c[16];      // conj W_16
  int tid = threadIdx.x;
  int sub = tid >> 6, lane = tid & 63;
  int g = blockIdx.x, s = blockIdx.y;
  int k2 = g*4 + sub;
  bool rowok = (k2 < 625);
  int k2v = rowok ? k2 : 0;

  // tables
  if (tid < 16){ float2 w = d_W16[tid]; shW16c[tid] = make_float2(w.x, -w.y); }
  if (tid >= 32 && tid < 96){
    int t2 = tid - 32;
    int rr = t2 >> 4, e = t2 & 15;
    int k2l = g*4 + rr;
    int k2c = (k2l < 625) ? k2l : 0;
    float2 wa = d_W[k2c * e];
    shAc[rr][e] = make_float2(wa.x, -wa.y);
  }
  if (tid >= 96 && tid < 160){
    int t2 = tid - 96;
    int rr = t2 >> 4, e = t2 & 15;
    int k2l = g*4 + rr;
    int k2c = (k2l < 625) ? k2l : 0;
    float2 wb = d_W[k2c * 16 * e];
    shBc[rr][e] = make_float2(wb.x, -wb.y);
  }
  for (int t = tid; t < 256; t += 256){
    int r = t >> 4, jj = t & 15;
    float2 w = d_W[625*r*jj];
    shW6[t] = make_float2(w.x, -w.y);
  }

  // load B[n1] for this k2 row and run forward FFT256 over n1
  const float2* in = d_work + s*LTOT + k2v*256;
  for (int i = lane; i < 256; i += 64) sh[sub][0][i] = in[i];
  __syncthreads();
  fft256s<-1>(sh[sub][0], sh[sub][1], lane);   // X in sh[sub][0]; ends with syncthreads

  // inverse phase thread mapping
  int row = sub;                 // 0..3 (same k2 row)
  int grp = lane >> 4;           // 0..3 band group
  int j   = lane & 15;
  float2* Tb = T[row*4 + grp];
  const float2* Xr = sh[row][0];
  bool special = (k2v == 0 && rowok);
  float2 acj = shAc[row][j];     // conj W^{k2*j}

  #pragma unroll
  for (int bi = 0; bi < 2; bi++){
    int b = 2*grp + bi;
    // ---- stage 1 (band-dependent, sparse) ----
    if (special){
      unsigned bm = 0;
      #pragma unroll
      for (int r = 0; r < 16; r++){
        int k1 = j + 16*r;
        int bnd = (k1==0) ? 7 : (((k1<=128)? (k1-1) : (255-k1)) >> 4);
        if (bnd == b) bm |= 1u<<r;
      }
      for (int so = 0; so < 16; so++){
        float2 acc = make_float2(0.f,0.f);
        for (int r = 0; r < 16; r++){
          if (bm & (1u<<r)) acc = cadd(acc, cmulf(Xr[j+16*r], shW16c[(r*so)&15]));
        }
        Tb[16*j + (so ^ j)] = acc;
      }
    } else {
      float2 lo = Xr[j + 16*b];
      float2 hi = Xr[j + 240 - 16*b];
      #pragma unroll
      for (int so = 0; so < 16; so++){
        float2 wl = shW16c[(b*so)&15];
        float2 wh = shW16c[((15-b)*so)&15];
        Tb[16*j + (so ^ j)] = cadd(cmulf(lo, wl), cmulf(hi, wh));
      }
    }
    __syncwarp();      // cross-lane transpose inside the 16-lane group

    // ---- stage 2: IFFT16 over r, in-place on lane-private slots ----
    #pragma unroll
    for (int r0 = 0; r0 < 4; r0++){
      float2 v[4];
      #pragma unroll
      for (int r2 = 0; r2 < 4; r2++){
        int r = r0 + 4*r2;
        v[r2] = cmulf(Tb[16*r + (j ^ r)], shW6[r*16 + j]);
      }
      dft4<1>(v);
      #pragma unroll
      for (int k0 = 0; k0 < 4; k0++){
        float2 c = (r0*k0) ? cmulf(v[k0], shW16c[(r0*k0)&15]) : v[k0];
        int sl = 4*k0 + r0;
        Tb[16*sl + (j ^ sl)] = c;
      }
    }
    #pragma unroll
    for (int k0 = 0; k0 < 4; k0++){
      float2 v[4];
      #pragma unroll
      for (int r0 = 0; r0 < 4; r0++){
        int sl = 4*k0 + r0;
        v[r0] = Tb[16*sl + (j ^ sl)];
      }
      dft4<1>(v);
      #pragma unroll
      for (int k1 = 0; k1 < 4; k1++){
        int q = k0 + 4*k1;
        float2 tw = cmulf(acj, shBc[row][q]);   // conj W^{k2*(j+16q)}
        float2 res = cmulf(v[k1], tw);
        int sl = 4*k0 + k1;
        Tb[16*sl + (j ^ sl)] = res;
      }
    }
    __syncthreads();   // all groups' T final before cooperative store

    // store bands {bi, 2+bi, 4+bi, 6+bi}: 4 bands x 256 n1 x 4 k2
    for (int idx = tid; idx < 4096; idx += 256){
      int bg  = idx >> 10;
      int rem = idx & 1023;
      int n1  = rem >> 2;
      int k2r = rem & 3;
      int k2w = g*4 + k2r;
      if (k2w < 625){
        int b2 = 2*bg + bi;
        int q = n1 >> 4;
        int sl = ((q & 3) << 2) | (q >> 2);
        int p = 16*sl + ((n1 & 15) ^ sl);
        d_work8[(size_t)(b2*8 + s)*LTOT + n1*625 + k2w] = T[k2r*4 + bg][p];
      }
    }
    __syncthreads();   // T reusable in next bi
  }
}

// ---------------- inverse stage 2 + energies ----------------
// Block: 128 threads = 5 n1-rows x 25 lanes; 4 pipes (bs8 values) per block,
// reusing the shWL table. Grid (NG2, 16).
#define IROWS 5
__global__ void __launch_bounds__(128) k_inv2_all(){
  __shared__ float2 buf[IROWS][25*26];
  __shared__ float  Psh[2][IROWS][156];
  __shared__ float2 shWL[625];       // conj W_L^{256*r*lane}  [r*25+lane]
  int tid = threadIdx.x;
  int row = tid / 25, lane = tid % 25;
  bool act = (tid < 125);
  int g = blockIdx.x;                // n1 group
  int n1 = g*IROWS + row;
  bool rowok = act && (n1 < 256);

  for (int t = tid; t < 625; t += 128){
    int r = t / 25, la = t - r*25;
    float2 w = d_W[256*r*la];
    shWL[t] = make_float2(w.x, -w.y);
  }
  __syncthreads();

  for (int ib = 0; ib < 4; ib++){
    int bs8 = blockIdx.y*4 + ib;     // b*8 + s
    int b = bs8 >> 3, s = bs8 & 7;

    float2 u[25];
    if (act){
      const float2* src = d_work8 + (size_t)bs8*LTOT + (size_t)(rowok ? n1 : 0)*625;
      float2 v[25];
      #pragma unroll
      for (int r=0;r<25;r++) v[r] = rowok ? src[lane + 25*r] : make_float2(0.f,0.f);
      dft25i(v);
      #pragma unroll
      for (int r=0;r<25;r++) buf[row][lane*26 + r] = v[r];
    }
    __syncthreads();
    if (act){
      #pragma unroll
      for (int r=0;r<25;r++)
        u[r] = cmulf(buf[row][r*26 + lane], shWL[r*25 + lane]);
      dft25i(u);                     // y_w + i*y_o at n2 = lane + 25r  (x L)
    }
    __syncthreads();
    float* eR = (float*)&buf[0][0];
    float* eI = eR + IROWS*625;
    const float invL = 1.0f/160000.0f;
    if (act){
      #pragma unroll
      for (int r=0;r<25;r++){
        int n2 = lane + 25*r;
        float yr = u[r].x * invL;
        float yi = u[r].y * invL;
        eR[row*625 + n2] = yr*yr;
        eI[row*625 + n2] = yi*yi;
      }
    }
    __syncthreads();
    for (int t = tid; t < IROWS*156; t += 128){
      int rr = t / 156, jb = t - rr*156;
      const float* e0 = eR + rr*625 + 4*jb;
      const float* e1 = eI + rr*625 + 4*jb;
      Psh[0][rr][jb] = (e0[0] + e0[1]) + (e0[2] + e0[3]);
      Psh[1][rr][jb] = (e1[0] + e1[1]) + (e1[2] + e1[3]);
    }
    __syncthreads();
    int bs1 = b*16 + s;        // watermarked
    int bs2 = b*16 + s + 8;    // original
    for (int t = tid; t < 2*156; t += 128){
      int half = t / 156, jb = t - half*156;
      float sum = ((Psh[half][0][jb] + Psh[half][1][jb]) +
                   (Psh[half][2][jb] + Psh[half][3][jb])) + Psh[half][4][jb];
      int bsx = half ? bs2 : bs1;
      d_P[((size_t)bsx*NBLK + jb)*NG2 + g] = sum;
    }
    __syncthreads();           // Psh/buf reusable by next pipe
  }
}

__global__ void k_red_all(){
  int idx = blockIdx.x*blockDim.x + threadIdx.x;
  if (idx < NBS*NBLK){
    const float* p = d_P + (size_t)idx*NG2;
    float sum = 0.f;
    #pragma unroll 4
    for (int i=0;i<NG2;i++) sum += p[i];
    d_blk[idx] = sum;
  }
}

// diffs + softmax(diff).diff in one block (diff array in shared)
__global__ void __launch_bounds__(1024) k_final(float* __restrict__ out){
  __shared__ float sdiff[NDIFF];
  __shared__ float redA[32];
  __shared__ float redB[32];
  int tid = threadIdx.x;
  for (int t = tid; t < NDIFF; t += 1024){
    int s = t / (8*NCH);
    int rem = t - s*(8*NCH);
    int b = rem / NCH, jb = rem - b*NCH;
    float ew = d_blk[(b*16+s)*NBLK + jb]   + d_blk[(b*16+s)*NBLK + jb + 1];
    float eo = d_blk[(b*16+s+8)*NBLK + jb] + d_blk[(b*16+s+8)*NBLK + jb + 1];
    float lw = 10.f*log10f(ew*(1.f/2048.f) + 1e-12f);
    float lo = 10.f*log10f(eo*(1.f/2048.f) + 1e-12f);
    sdiff[t] = lw - lo;
  }
  __syncthreads();
  float m = -1e30f;
  for (int i = tid; i < NDIFF; i += 1024) m = fmaxf(m, sdiff[i]);
  #pragma unroll
  for (int o = 16; o; o >>= 1) m = fmaxf(m, __shfl_xor_sync(~0u, m, o));
  if ((tid & 31) == 0) redA[tid >> 5] = m;
  __syncthreads();
  {
    float v = redA[tid & 31];
    #pragma unroll
    for (int o = 16; o; o >>= 1) v = fmaxf(v, __shfl_xor_sync(~0u, v, o));
    m = v;                              // full max in every thread
  }
  __syncthreads();
  float se = 0.f, sw = 0.f;
  for (int i = tid; i < NDIFF; i += 1024){
    float d = sdiff[i];
    float e = expf(d - m);
    se += e;
    sw = fmaf(e, d, sw);
  }
  #pragma unroll
  for (int o = 16; o; o >>= 1){
    se += __shfl_xor_sync(~0u, se, o);
    sw += __shfl_xor_sync(~0u, sw, o);
  }
  if ((tid & 31) == 0){ redA[tid >> 5] = se; redB[tid >> 5] = sw; }
  __syncthreads();
  if (tid == 0){
    float s1 = 0.f, s2 = 0.f;
    #pragma unroll
    for (int i = 0; i < 32; i++){ s1 += redA[i]; s2 += redB[i]; }
    out[0] = s2 / s1;
  }
}

extern "C" void kernel_launch(void* const* d_in, const int* in_sizes, int n_in,
                              void* d_out, int out_size){
  const float* xw = (const float*)d_in[0];
  const float* xo = (const float*)d_in[1];
  float* out = (float*)d_out;

  k_genW<<<(LTOT+255)/256, 256>>>();
  k_fwd1<<<dim3(64,8), 512>>>(xw, xo);
  k_f2i1<<<dim3(157,8), 256>>>();          // fused fwd2 + inv1 (157*4 = 628 >= 625)
  k_inv2_all<<<dim3(NG2,16), 128>>>();     // 4 pipes per block
  k_red_all<<<(NBS*NBLK+255)/256, 256>>>();
  k_final<<<1, 1024>>>(out);
}

// round 17
// speedup vs baseline: 1.0949x; 1.0949x over previous
#include <cuda_runtime.h>

// TFLoudnessLoss: multi-band (8) loudness difference with softmax weighting.
// Four-step FFT:  n = n1 + 256*n2,  k = k2 + 625*k1   (L = 160000 = 256*625)
// Packing: z_s = xw[s] + i*xo[s] (8 packed signals). Band mask is conjugate-
// symmetric, so IFFT(mask_b * Z) = r_w + i*r_o directly (both real).
// Band structure: with k1 = j + 16 r, for k2>=1 band(k2+625*k1) = r<8 ? r : 15-r.
// fwd2+inv1 fused. inv2 = single-pipe, immediate W25 twiddles.
// dft5 = factored radix-5 butterfly (~42 real ops vs ~112 naive).

#define LTOT 160000
#define NBLK 156
#define NCH  155
#define NDIFF (8*8*155)
#define NBS 128            /* 8 bands x 16 signals (w:0-7, o:8-15) */
#define NPIPE 64           /* 8 bands x 8 packed signals */
#define NG2  52            /* inv2 n1-groups: 52*5 >= 260 >= 256 */

__device__ float2 d_W[LTOT];              // e^{-2*pi*i*m/L}
__device__ float2 d_W16[16];
__device__ float2 d_work[8*LTOT];         // fwd intermediate [s][k2*256+n1]
__device__ float2 d_work8[(size_t)NPIPE*LTOT];  // inv intermediate [b*8+s][n1*625+k2]
__device__ float  d_P[NBS*NBLK*NG2];      // partial block energies [bs][jb][g]
__device__ float  d_blk[NBS*NBLK];

__device__ __forceinline__ float2 cmulf(float2 a, float2 b){
  return make_float2(fmaf(a.x,b.x,-a.y*b.y), fmaf(a.x,b.y,a.y*b.x));
}
__device__ __forceinline__ float2 cadd(float2 a,float2 b){return make_float2(a.x+b.x,a.y+b.y);}
__device__ __forceinline__ float2 csub(float2 a,float2 b){return make_float2(a.x-b.x,a.y-b.y);}

__global__ void k_genW(){
  int m = blockIdx.x*blockDim.x + threadIdx.x;
  if (m < LTOT){
    float t = (float)((double)m / 80000.0);   // 2m/L
    float s, c;
    sincospif(t, &s, &c);
    d_W[m] = make_float2(c, -s);
  }
  if (blockIdx.x == 0 && threadIdx.x < 16){
    int q = threadIdx.x;
    float s, c; sincospif(2.f*q/16.f, &s, &c);
    d_W16[q] = make_float2(c, -s);
  }
}

// Factored radix-5 butterfly: y_k = sum_n x_n e^{SIGN*2pi*i*nk/5}
template<int SIGN>
__device__ __forceinline__ void dft5(float2 v[5]){
  const float S1 = 0.95105651629515353f;   // sin(2pi/5)
  const float S2 = 0.58778525229247314f;   // sin(4pi/5)
  const float Q  = 0.55901699437494742f;   // sqrt(5)/4
  float2 t1 = cadd(v[1], v[4]);
  float2 t2 = cadd(v[2], v[3]);
  float2 t3 = csub(v[1], v[4]);
  float2 t4 = csub(v[2], v[3]);
  float2 u  = cadd(t1, t2);
  float2 y0 = cadd(v[0], u);
  float2 vv = make_float2(fmaf(-0.25f, u.x, v[0].x), fmaf(-0.25f, u.y, v[0].y));
  float2 d  = csub(t1, t2);
  float2 w  = make_float2(Q*d.x, Q*d.y);
  float2 a1 = cadd(vv, w);
  float2 a2 = csub(vv, w);
  float2 b1 = make_float2(fmaf(S1, t3.x, S2*t4.x), fmaf(S1, t3.y, S2*t4.y));
  float2 b2 = make_float2(fmaf(S2, t3.x, -S1*t4.x), fmaf(S2, t3.y, -S1*t4.y));
  // y1 = a1 + SIGN*i*b1 ; y4 = a1 - SIGN*i*b1 ; y2 = a2 + SIGN*i*b2 ; y3 = a2 - SIGN*i*b2
  float2 ib1 = make_float2(-SIGN*b1.y, SIGN*b1.x);
  float2 ib2 = make_float2(-SIGN*b2.y, SIGN*b2.x);
  v[0] = y0;
  v[1] = cadd(a1, ib1);
  v[2] = cadd(a2, ib2);
  v[3] = csub(a2, ib2);
  v[4] = csub(a1, ib1);
}

template<int SIGN>
__device__ __forceinline__ void dft4(float2 v[4]){
  float2 s02 = cadd(v[0],v[2]), d02 = csub(v[0],v[2]);
  float2 s13 = cadd(v[1],v[3]), d13 = csub(v[1],v[3]);
  float2 id13 = make_float2(-d13.y, d13.x);
  float2 o0 = cadd(s02, s13);
  float2 o2 = csub(s02, s13);
  float2 o1, o3;
  if (SIGN < 0){ o1 = csub(d02, id13); o3 = cadd(d02, id13); }
  else         { o1 = cadd(d02, id13); o3 = csub(d02, id13); }
  v[0]=o0; v[1]=o1; v[2]=o2; v[3]=o3;
}

// conj(W25^m) = cos(2pi m/25) + i sin(2pi m/25), m compile-time (folds to imm)
__device__ __forceinline__ float2 w25im(int m){
  switch(m){
    case 1:  return make_float2( 0.96858316112863f,  0.24868988716485f);
    case 2:  return make_float2( 0.87630668004386f,  0.48175367410172f);
    case 3:  return make_float2( 0.72896862742141f,  0.68454710592869f);
    case 4:  return make_float2( 0.53582679497900f,  0.84432792550202f);
    case 6:  return make_float2( 0.06279051952931f,  0.99802672842827f);
    case 8:  return make_float2(-0.42577929156507f,  0.90482705246602f);
    case 9:  return make_float2(-0.63742398974869f,  0.77051324277579f);
    case 12: return make_float2(-0.99211470131448f,  0.12533323356430f);
    case 16: return make_float2(-0.63742398974869f, -0.77051324277579f);
    default: return make_float2(1.f, 0.f);
  }
}

// inverse DFT25 with immediate-constant twiddles
__device__ __forceinline__ void dft25i(float2 v[25]){
  float2 t[25];
  #pragma unroll
  for (int r0=0;r0<5;r0++){
    float2 a[5] = {v[r0], v[r0+5], v[r0+10], v[r0+15], v[r0+20]};
    dft5<1>(a);
    #pragma unroll
    for (int k0=0;k0<5;k0++)
      t[r0*5+k0] = (r0*k0) ? cmulf(a[k0], w25im(r0*k0)) : a[k0];
  }
  #pragma unroll
  for (int k0=0;k0<5;k0++){
    float2 b[5] = {t[k0], t[5+k0], t[10+k0], t[15+k0], t[20+k0]};
    dft5<1>(b);
    #pragma unroll
    for (int k1=0;k1<5;k1++) v[k0+5*k1] = b[k1];
  }
}

// ---------------- shared-memory Stockham FFTs ----------------

template<int SIGN>
__device__ void fft625(float2* __restrict__ A, float2* __restrict__ B, int lane){
  float2* src = A; float2* dst = B;
  int Ns = 1;
  #pragma unroll
  for (int t=0;t<4;t++){
    if (lane < 125){
      int j = lane;
      int jNs = j % Ns;
      int f = LTOT/(Ns*5);
      float2 v[5];
      #pragma unroll
      for (int r=0;r<5;r++){
        float2 x = src[j + r*125];
        int m = r*jNs*f;
        if (m){
          float2 w = d_W[m];
          if (SIGN>0) w.y = -w.y;
          x = cmulf(x,w);
        }
        v[r]=x;
      }
      dft5<SIGN>(v);
      int idxD = (j/Ns)*(Ns*5) + jNs;
      #pragma unroll
      for (int r=0;r<5;r++) dst[idxD + r*Ns] = v[r];
    }
    __syncthreads();
    float2* tmp = src; src = dst; dst = tmp;
    Ns *= 5;
  }
}

template<int SIGN>
__device__ void fft256s(float2* __restrict__ A, float2* __restrict__ B, int lane){
  float2* src = A; float2* dst = B;
  int Ns = 1;
  #pragma unroll
  for (int t=0;t<4;t++){
    {
      int j = lane;
      int jNs = j % Ns;
      int f = LTOT/(Ns*4);
      float2 v[4];
      #pragma unroll
      for (int r=0;r<4;r++){
        float2 x = src[j + r*64];
        int m = r*jNs*f;
        if (m){
          float2 w = d_W[m];
          if (SIGN>0) w.y = -w.y;
          x = cmulf(x,w);
        }
        v[r]=x;
      }
      dft4<SIGN>(v);
      int idxD = (j/Ns)*(Ns*4) + jNs;
      #pragma unroll
      for (int r=0;r<4;r++) dst[idxD + r*Ns] = v[r];
    }
    __syncthreads();
    float2* tmp = src; src = dst; dst = tmp;
    Ns *= 4;
  }
}

// ---------------- forward stage 1 ----------------

// z = xw + i*xo : 8 packed signals
__global__ void __launch_bounds__(512) k_fwd1(const float* __restrict__ xw, const float* __restrict__ xo){
  __shared__ float2 sh[4][2][625];
  int tid = threadIdx.x;
  int sub = tid >> 7, lane = tid & 127;
  int n1b = blockIdx.x*4;
  int s   = blockIdx.y;             // 0..7
  const float* xa = xw + s*LTOT;
  const float* xb = xo + s*LTOT;
  for (int w = tid; w < 2500; w += 512){
    int n2 = w >> 2, sb = w & 3;
    int n = n1b + sb + 256*n2;
    sh[sb][0][n2] = make_float2(xa[n], xb[n]);
  }
  __syncthreads();
  fft625<-1>(sh[sub][0], sh[sub][1], lane);
  float2* out = d_work + s*LTOT;
  for (int w = tid; w < 2500; w += 512){
    int k2 = w >> 2, sb = w & 3;
    int n1 = n1b + sb;
    float2 v = cmulf(sh[sb][0][k2], d_W[n1*k2]);
    out[k2*256 + n1] = v;
  }
}

// ---------------- fused forward stage 2 + inverse stage 1 ----------------
// Block: 256 threads. FFT phase: 4 k2-rows x 64 lanes (forward FFT256 over n1).
// Inverse phase: 4 rows x 4 band-groups x 16 lanes; group bg handles bands
// 2bg and 2bg+1 sequentially with the in-place IFFT16 slot scheme.
// Grid: (157 k2-groups, 8 signals).
__global__ void __launch_bounds__(256) k_f2i1(){
  __shared__ float2 sh[4][2][256];   // 16KB fft buffers; X stays in sh[row][0]
  __shared__ float2 T[16][257];      // 32.9KB: [row*4 + grp]
  __shared__ float2 shW6[256];       // conj W_L^{625*r*j}  [r*16+j]
  __shared__ float2 shAc[4][16];     // conj W_L^{k2*l},    l<16
  __shared__ float2 shBc[4][16];     // conj W_L^{k2*16*h}, h<16
  __shared__ float2 shW16c[16];      // conj W_16
  int tid = threadIdx.x;
  int sub = tid >> 6, lane = tid & 63;
  int g = blockIdx.x, s = blockIdx.y;
  int k2 = g*4 + sub;
  bool rowok = (k2 < 625);
  int k2v = rowok ? k2 : 0;

  // tables
  if (tid < 16){ float2 w = d_W16[tid]; shW16c[tid] = make_float2(w.x, -w.y); }
  if (tid >= 32 && tid < 96){
    int t2 = tid - 32;
    int rr = t2 >> 4, e = t2 & 15;
    int k2l = g*4 + rr;
    int k2c = (k2l < 625) ? k2l : 0;
    float2 wa = d_W[k2c * e];
    shAc[rr][e] = make_float2(wa.x, -wa.y);
  }
  if (tid >= 96 && tid < 160){
    int t2 = tid - 96;
    int rr = t2 >> 4, e = t2 & 15;
    int k2l = g*4 + rr;
    int k2c = (k2l < 625) ? k2l : 0;
    float2 wb = d_W[k2c * 16 * e];
    shBc[rr][e] = make_float2(wb.x, -wb.y);
  }
  for (int t = tid; t < 256; t += 256){
    int r = t >> 4, jj = t & 15;
    float2 w = d_W[625*r*jj];
    shW6[t] = make_float2(w.x, -w.y);
  }

  // load B[n1] for this k2 row and run forward FFT256 over n1
  const float2* in = d_work + s*LTOT + k2v*256;
  for (int i = lane; i < 256; i += 64) sh[sub][0][i] = in[i];
  __syncthreads();
  fft256s<-1>(sh[sub][0], sh[sub][1], lane);   // X in sh[sub][0]; ends with syncthreads

  // inverse phase thread mapping
  int row = sub;                 // 0..3 (same k2 row)
  int grp = lane >> 4;           // 0..3 band group
  int j   = lane & 15;
  float2* Tb = T[row*4 + grp];
  const float2* Xr = sh[row][0];
  bool special = (k2v == 0 && rowok);
  float2 acj = shAc[row][j];     // conj W^{k2*j}

  #pragma unroll
  for (int bi = 0; bi < 2; bi++){
    int b = 2*grp + bi;
    // ---- stage 1 (band-dependent, sparse) ----
    if (special){
      unsigned bm = 0;
      #pragma unroll
      for (int r = 0; r < 16; r++){
        int k1 = j + 16*r;
        int bnd = (k1==0) ? 7 : (((k1<=128)? (k1-1) : (255-k1)) >> 4);
        if (bnd == b) bm |= 1u<<r;
      }
      for (int so = 0; so < 16; so++){
        float2 acc = make_float2(0.f,0.f);
        for (int r = 0; r < 16; r++){
          if (bm & (1u<<r)) acc = cadd(acc, cmulf(Xr[j+16*r], shW16c[(r*so)&15]));
        }
        Tb[16*j + (so ^ j)] = acc;
      }
    } else {
      float2 lo = Xr[j + 16*b];
      float2 hi = Xr[j + 240 - 16*b];
      #pragma unroll
      for (int so = 0; so < 16; so++){
        float2 wl = shW16c[(b*so)&15];
        float2 wh = shW16c[((15-b)*so)&15];
        Tb[16*j + (so ^ j)] = cadd(cmulf(lo, wl), cmulf(hi, wh));
      }
    }
    __syncwarp();      // cross-lane transpose inside the 16-lane group

    // ---- stage 2: IFFT16 over r, in-place on lane-private slots ----
    #pragma unroll
    for (int r0 = 0; r0 < 4; r0++){
      float2 v[4];
      #pragma unroll
      for (int r2 = 0; r2 < 4; r2++){
        int r = r0 + 4*r2;
        v[r2] = cmulf(Tb[16*r + (j ^ r)], shW6[r*16 + j]);
      }
      dft4<1>(v);
      #pragma unroll
      for (int k0 = 0; k0 < 4; k0++){
        float2 c = (r0*k0) ? cmulf(v[k0], shW16c[(r0*k0)&15]) : v[k0];
        int sl = 4*k0 + r0;
        Tb[16*sl + (j ^ sl)] = c;
      }
    }
    #pragma unroll
    for (int k0 = 0; k0 < 4; k0++){
      float2 v[4];
      #pragma unroll
      for (int r0 = 0; r0 < 4; r0++){
        int sl = 4*k0 + r0;
        v[r0] = Tb[16*sl + (j ^ sl)];
      }
      dft4<1>(v);
      #pragma unroll
      for (int k1 = 0; k1 < 4; k1++){
        int q = k0 + 4*k1;
        float2 tw = cmulf(acj, shBc[row][q]);   // conj W^{k2*(j+16q)}
        float2 res = cmulf(v[k1], tw);
        int sl = 4*k0 + k1;
        Tb[16*sl + (j ^ sl)] = res;
      }
    }
    __syncthreads();   // all groups' T final before cooperative store

    // store bands {bi, 2+bi, 4+bi, 6+bi}: 4 bands x 256 n1 x 4 k2
    for (int idx = tid; idx < 4096; idx += 256){
      int bg  = idx >> 10;
      int rem = idx & 1023;
      int n1  = rem >> 2;
      int k2r = rem & 3;
      int k2w = g*4 + k2r;
      if (k2w < 625){
        int b2 = 2*bg + bi;
        int q = n1 >> 4;
        int sl = ((q & 3) << 2) | (q >> 2);
        int p = 16*sl + ((n1 & 15) ^ sl);
        d_work8[(size_t)(b2*8 + s)*LTOT + n1*625 + k2w] = T[k2r*4 + bg][p];
      }
    }
    __syncthreads();   // T reusable in next bi
  }
}

// ---------------- inverse stage 2 + energies: 64 (band, packed signal) ----------------
#define IROWS 5
__global__ void __launch_bounds__(128) k_inv2_all(){
  __shared__ float2 buf[IROWS][25*26];
  __shared__ float  Psh[2][IROWS][156];
  __shared__ float2 shWL[625];       // conj W_L^{256*r*lane}  [r*25+lane]
  int tid = threadIdx.x;
  int row = tid / 25, lane = tid % 25;
  bool act = (tid < 125);
  int g = blockIdx.x;                // n1 group
  int bs8 = blockIdx.y;              // b*8 + s
  int b = bs8 >> 3, s = bs8 & 7;
  int n1 = g*IROWS + row;
  bool rowok = act && (n1 < 256);

  for (int t = tid; t < 625; t += 128){
    int r = t / 25, la = t - r*25;
    float2 w = d_W[256*r*la];
    shWL[t] = make_float2(w.x, -w.y);
  }
  __syncthreads();

  float2 u[25];
  if (act){
    const float2* src = d_work8 + (size_t)bs8*LTOT + (size_t)(rowok ? n1 : 0)*625;
    float2 v[25];
    #pragma unroll
    for (int r=0;r<25;r++) v[r] = rowok ? src[lane + 25*r] : make_float2(0.f,0.f);
    dft25i(v);
    #pragma unroll
    for (int r=0;r<25;r++) buf[row][lane*26 + r] = v[r];
  }
  __syncthreads();
  if (act){
    #pragma unroll
    for (int r=0;r<25;r++)
      u[r] = cmulf(buf[row][r*26 + lane], shWL[r*25 + lane]);
    dft25i(u);                       // y_w + i*y_o at n2 = lane + 25r  (x L)
  }
  __syncthreads();
  float* eR = (float*)&buf[0][0];
  float* eI = eR + IROWS*625;
  const float invL = 1.0f/160000.0f;
  if (act){
    #pragma unroll
    for (int r=0;r<25;r++){
      int n2 = lane + 25*r;
      float yr = u[r].x * invL;
      float yi = u[r].y * invL;
      eR[row*625 + n2] = yr*yr;
      eI[row*625 + n2] = yi*yi;
    }
  }
  __syncthreads();
  for (int t = tid; t < IROWS*156; t += 128){
    int rr = t / 156, jb = t - rr*156;
    const float* e0 = eR + rr*625 + 4*jb;
    const float* e1 = eI + rr*625 + 4*jb;
    Psh[0][rr][jb] = (e0[0] + e0[1]) + (e0[2] + e0[3]);
    Psh[1][rr][jb] = (e1[0] + e1[1]) + (e1[2] + e1[3]);
  }
  __syncthreads();
  int bs1 = b*16 + s;        // watermarked
  int bs2 = b*16 + s + 8;    // original
  for (int t = tid; t < 2*156; t += 128){
    int half = t / 156, jb = t - half*156;
    float sum = ((Psh[half][0][jb] + Psh[half][1][jb]) +
                 (Psh[half][2][jb] + Psh[half][3][jb])) + Psh[half][4][jb];
    int bsx = half ? bs2 : bs1;
    d_P[((size_t)bsx*NBLK + jb)*NG2 + g] = sum;
  }
}

__global__ void k_red_all(){
  int idx = blockIdx.x*blockDim.x + threadIdx.x;
  if (idx < NBS*NBLK){
    const float* p = d_P + (size_t)idx*NG2;
    float sum = 0.f;
    #pragma unroll 4
    for (int i=0;i<NG2;i++) sum += p[i];
    d_blk[idx] = sum;
  }
}

// diffs + softmax(diff).diff in one block (diff array in shared)
__global__ void __launch_bounds__(1024) k_final(float* __restrict__ out){
  __shared__ float sdiff[NDIFF];
  __shared__ float redA[32];
  __shared__ float redB[32];
  int tid = threadIdx.x;
  for (int t = tid; t < NDIFF; t += 1024){
    int s = t / (8*NCH);
    int rem = t - s*(8*NCH);
    int b = rem / NCH, jb = rem - b*NCH;
    float ew = d_blk[(b*16+s)*NBLK + jb]   + d_blk[(b*16+s)*NBLK + jb + 1];
    float eo = d_blk[(b*16+s+8)*NBLK + jb] + d_blk[(b*16+s+8)*NBLK + jb + 1];
    float lw = 10.f*log10f(ew*(1.f/2048.f) + 1e-12f);
    float lo = 10.f*log10f(eo*(1.f/2048.f) + 1e-12f);
    sdiff[t] = lw - lo;
  }
  __syncthreads();
  float m = -1e30f;
  for (int i = tid; i < NDIFF; i += 1024) m = fmaxf(m, sdiff[i]);
  #pragma unroll
  for (int o = 16; o; o >>= 1) m = fmaxf(m, __shfl_xor_sync(~0u, m, o));
  if ((tid & 31) == 0) redA[tid >> 5] = m;
  __syncthreads();
  {
    float v = redA[tid & 31];
    #pragma unroll
    for (int o = 16; o; o >>= 1) v = fmaxf(v, __shfl_xor_sync(~0u, v, o));
    m = v;                              // full max in every thread
  }
  __syncthreads();
  float se = 0.f, sw = 0.f;
  for (int i = tid; i < NDIFF; i += 1024){
    float d = sdiff[i];
    float e = expf(d - m);
    se += e;
    sw = fmaf(e, d, sw);
  }
  #pragma unroll
  for (int o = 16; o; o >>= 1){
    se += __shfl_xor_sync(~0u, se, o);
    sw += __shfl_xor_sync(~0u, sw, o);
  }
  if ((tid & 31) == 0){ redA[tid >> 5] = se; redB[tid >> 5] = sw; }
  __syncthreads();
  if (tid == 0){
    float s1 = 0.f, s2 = 0.f;
    #pragma unroll
    for (int i = 0; i < 32; i++){ s1 += redA[i]; s2 += redB[i]; }
    out[0] = s2 / s1;
  }
}

extern "C" void kernel_launch(void* const* d_in, const int* in_sizes, int n_in,
                              void* d_out, int out_size){
  const float* xw = (const float*)d_in[0];
  const float* xo = (const float*)d_in[1];
  float* out = (float*)d_out;

  k_genW<<<(LTOT+255)/256, 256>>>();
  k_fwd1<<<dim3(64,8), 512>>>(xw, xo);
  k_f2i1<<<dim3(157,8), 256>>>();          // fused fwd2 + inv1 (157*4 = 628 >= 625)
  k_inv2_all<<<dim3(NG2,NPIPE), 128>>>();  // 52*5 = 260 >= 256 n1 rows
  k_red_all<<<(NBS*NBLK+255)/256, 256>>>();
  k_final<<<1, 1024>>>(out);
}